// round 14
// baseline (speedup 1.0000x reference)
#include <cuda_runtime.h>
#include <cuda_bf16.h>
#include <cstdint>

#define HID   2048
#define KSEL  256
#define NTOK  16384
#define NTHR  256
#define FULLW 0xFFFFFFFFu
// Bin-aligned filter key: key2f(0xBF600000) = 0.875, bin = 1531.
#define THR0  0xBF600000u
#define SENT  0xFFFFFFFFu
#define NB    768            // scan window width (bins), 3 per thread
#define WBASE 1280           // fast-path window base: bins [1280, 2048)

__device__ int g_ids64;

// Detect int32 vs int64 ids (odd 32-bit words all zero => int64).
__global__ void detect_ids_kernel(const unsigned int* __restrict__ w) {
    __shared__ unsigned acc[NTHR];
    unsigned v = 0;
    for (int i = threadIdx.x; i < NTOK / 2; i += NTHR) v |= w[2 * i + 1];
    acc[threadIdx.x] = v;
    __syncthreads();
    for (int s = NTHR / 2; s > 0; s >>= 1) {
        if (threadIdx.x < s) acc[threadIdx.x] |= acc[threadIdx.x + s];
        __syncthreads();
    }
    if (threadIdx.x == 0) g_ids64 = (acc[0] == 0u) ? 1 : 0;
}

__device__ __forceinline__ unsigned f2key(float f) {
    unsigned u = __float_as_uint(f);
    return u ^ ((u & 0x80000000u) ? 0xFFFFFFFFu : 0x80000000u);
}
__device__ __forceinline__ float key2f(unsigned u) {
    unsigned b = (u & 0x80000000u) ? (u ^ 0x80000000u) : ~u;
    return __uint_as_float(b);
}

struct SmemT {
    unsigned ctr[NB];                // 3KB: window histogram -> scatter cursors
    unsigned long long sk[KSEL];     // 2KB: survivors
    unsigned cand[2048];             // 8KB: packed threshold-bin candidates
    float2 outVI[KSEL];              // 2KB: staged (value, index)
    unsigned warpTot[8];
    unsigned s_b, s_rem;
    unsigned cntN, cntG;
};  // ~15.2KB

__global__ __launch_bounds__(NTHR, 6) void topk_kernel(
    const void* __restrict__ ids_raw,
    const float* __restrict__ W,
    float* __restrict__ out_val,
    float* __restrict__ out_idx)
{
    __shared__ SmemT s;
    const int tok  = blockIdx.x;
    const int tid  = threadIdx.x;
    const int lane = tid & 31;
    const int wrp  = tid >> 5;

    if (tid == 0) { s.cntN = 0u; s.cntG = 0u; s.s_b = SENT; }

    // ---- gather one embedding row (coalesced float4) ----
    long long id;
    if (g_ids64) id = ((const long long*)ids_raw)[tok];
    else         id = (long long)((const int*)ids_raw)[tok];

    const float4* row = (const float4*)(W + (size_t)id * HID);
    float4 a = __ldg(row + tid);
    float4 b = __ldg(row + tid + NTHR);

    unsigned key[8];
    key[0] = f2key(a.x); key[1] = f2key(a.y); key[2] = f2key(a.z); key[3] = f2key(a.w);
    key[4] = f2key(b.x); key[5] = f2key(b.y); key[6] = f2key(b.z); key[7] = f2key(b.w);

    // ---- windowed, filtered 11-bit histogram + suffix scan ----
    // Fast path: window [1280,2048), elements filtered to key >= 0.875-key
    // (bin >= 1531). Rare fallback: unfiltered, sliding window, exact.
    unsigned thr = THR0;
    int win_lo = WBASE, win_hi = 2048;
    unsigned above = 0;                 // elements in windows already processed
    unsigned pb[3];
    bool fast = true;

    for (;;) {
        if (tid < NB / 8) ((uint4*)s.ctr)[tid * 2]     = make_uint4(0,0,0,0);
        if (tid < NB / 8) ((uint4*)s.ctr)[tid * 2 + 1] = make_uint4(0,0,0,0);
        __syncthreads();

        #pragma unroll
        for (int e = 0; e < 8; e++) {
            unsigned k = key[e];
            int d = (int)(k >> 21);
            if (k >= thr && d >= win_lo && d < win_hi)
                atomicAdd(&s.ctr[d - win_lo], 1u);
        }
        __syncthreads();

        unsigned bins[3];
        bins[0] = s.ctr[tid * 3];
        bins[1] = s.ctr[tid * 3 + 1];
        bins[2] = s.ctr[tid * 3 + 2];
        unsigned tsum = bins[0] + bins[1] + bins[2];

        unsigned sfx = tsum;            // sum over lanes >= mine
        #pragma unroll
        for (int off = 1; off < 32; off <<= 1) {
            unsigned y = __shfl_down_sync(FULLW, sfx, off);
            if (lane + off < 32) sfx += y;
        }
        if (lane == 0) s.warpTot[wrp] = sfx;
        __syncthreads();

        unsigned hiW = 0, wtot = 0;
        #pragma unroll
        for (int w = 0; w < 8; w++) {
            unsigned t = s.warpTot[w];
            wtot += t;
            if (w > wrp) hiW += t;
        }

        unsigned run = above + hiW + (sfx - tsum);
        #pragma unroll
        for (int i = 2; i >= 0; i--) {
            unsigned h = bins[i];
            pb[i] = run;
            if (run < KSEL && KSEL <= run + h) {
                s.s_b   = (unsigned)(win_lo + tid * 3 + i);
                s.s_rem = KSEL - run;
            }
            run += h;
        }
        __syncthreads();

        if (s.s_b != SENT) break;
        // Not found: exact fallback machinery (runs with prob ~1e-10).
        fast = false;
        if (thr != 0u) { thr = 0u; }                     // redo window unfiltered
        else { above += wtot; win_hi = win_lo; win_lo = win_hi - NB;
               if (win_lo < 0) win_lo = 0; }
        __syncthreads();                                 // protect ctr re-zero
    }

    const unsigned bsel = s.s_b;
    const unsigned rem  = s.s_rem;
    const int      nG   = (int)(KSEL - rem);

    if (fast) {
        // Seed scatter cursors with posBase: ctr[x] -> pb (window-local).
        s.ctr[tid * 3]     = pb[0];
        s.ctr[tid * 3 + 1] = pb[1];
        s.ctr[tid * 3 + 2] = pb[2];
        __syncthreads();

        // ---- scatter: survivors to bin segments, candidates packed ----
        #pragma unroll
        for (int e = 0; e < 8; e++) {
            unsigned k = key[e];
            unsigned d = k >> 21;
            if (d < bsel) continue;
            int idx = (e < 4) ? (tid * 4 + e) : ((tid + NTHR) * 4 + (e - 4));
            if (d > bsel) {
                unsigned slot = atomicAdd(&s.ctr[d - WBASE], 1u);
                s.sk[slot] = ((unsigned long long)k << 32) | (unsigned)(~idx);
            } else {
                unsigned slot = atomicAdd(&s.cntN, 1u);
                s.cand[slot] = ((k & 0x1FFFFFu) << 11) | (0x7FFu ^ (unsigned)idx);
            }
        }
        __syncthreads();

        // ---- survivors: rank within bin segment [ctr[d+1], ctr[d]) ----
        if (tid < nG) {
            unsigned long long my = s.sk[tid];
            const unsigned d = (unsigned)(my >> 53);
            unsigned lo = (d == 2047u) ? 0u : s.ctr[d + 1 - WBASE];
            unsigned hi = s.ctr[d - WBASE];
            int rank = 0;
            for (unsigned j = lo; j < hi; j++)
                rank += (s.sk[j] > my);
            s.outVI[lo + rank] = make_float2(key2f((unsigned)(my >> 32)),
                                             (float)((int)(~(unsigned)my)));
        }
    } else {
        // ---- exact generic path (astronomically rare) ----
        #pragma unroll
        for (int e = 0; e < 8; e++) {
            unsigned k = key[e];
            unsigned d = k >> 21;
            if (d < bsel) continue;
            int idx = (e < 4) ? (tid * 4 + e) : ((tid + NTHR) * 4 + (e - 4));
            if (d > bsel) {
                unsigned slot = atomicAdd(&s.cntG, 1u);
                s.sk[slot] = ((unsigned long long)k << 32) | (unsigned)(~idx);
            } else {
                unsigned slot = atomicAdd(&s.cntN, 1u);
                s.cand[slot] = ((k & 0x1FFFFFu) << 11) | (0x7FFu ^ (unsigned)idx);
            }
        }
        __syncthreads();
        if (tid < nG) {
            unsigned long long my = s.sk[tid];
            int rank = 0;
            for (int j = 0; j < nG; j++) rank += (s.sk[j] > my);
            s.outVI[rank] = make_float2(key2f((unsigned)(my >> 32)),
                                        (float)((int)(~(unsigned)my)));
        }
    }

    const int n1 = (int)s.cntN;

    // ---- threshold bin: rank-select top `rem` into slots [nG, 256) ----
    for (int t = tid; t < n1; t += NTHR) {
        unsigned my = s.cand[t];
        int rank = 0;
        for (int j = 0; j < n1; j++) rank += (s.cand[j] > my);
        if (rank < (int)rem) {
            unsigned k   = (bsel << 21) | (my >> 11);
            unsigned idx = 0x7FFu ^ (my & 0x7FFu);
            s.outVI[nG + rank] = make_float2(key2f(k), (float)idx);
        }
    }
    __syncthreads();

    // ---- single fully-coalesced global write ----
    float2 r = s.outVI[tid];
    out_val[(size_t)tok * KSEL + tid] = r.x;
    out_idx[(size_t)tok * KSEL + tid] = r.y;
}

extern "C" void kernel_launch(void* const* d_in, const int* in_sizes, int n_in,
                              void* d_out, int out_size)
{
    const void*  ids = d_in[0];
    const float* W   = (const float*)d_in[1];

    float* out_val = (float*)d_out;
    float* out_idx = (float*)d_out + (size_t)NTOK * KSEL;

    detect_ids_kernel<<<1, NTHR>>>((const unsigned int*)ids);
    topk_kernel<<<NTOK, NTHR>>>(ids, W, out_val, out_idx);
}

// round 15
// speedup vs baseline: 1.6953x; 1.6953x over previous
#include <cuda_runtime.h>
#include <cuda_bf16.h>
#include <cstdint>

#define HID   2048
#define KSEL  256
#define NTOK  16384
#define NTHR  256
#define FULLW 0xFFFFFFFFu
// Bin-aligned filter: key2f(0xBF600000)=0.875; k >= THR0 <=> (k>>21) >= 1531.
#define THR0  0xBF600000u
#define SENT  0xFFFFFFFFu
#define WBASE 1024           // scanned bins [1024, 2048): 4 per thread, uint4

__device__ int g_ids64;

// Detect int32 vs int64 ids (odd 32-bit words all zero => int64).
__global__ void detect_ids_kernel(const unsigned int* __restrict__ w) {
    __shared__ unsigned acc[NTHR];
    unsigned v = 0;
    for (int i = threadIdx.x; i < NTOK / 2; i += NTHR) v |= w[2 * i + 1];
    acc[threadIdx.x] = v;
    __syncthreads();
    for (int s = NTHR / 2; s > 0; s >>= 1) {
        if (threadIdx.x < s) acc[threadIdx.x] |= acc[threadIdx.x + s];
        __syncthreads();
    }
    if (threadIdx.x == 0) g_ids64 = (acc[0] == 0u) ? 1 : 0;
}

__device__ __forceinline__ unsigned f2key(float f) {
    unsigned u = __float_as_uint(f);
    return u ^ ((u & 0x80000000u) ? 0xFFFFFFFFu : 0x80000000u);
}
__device__ __forceinline__ float key2f(unsigned u) {
    unsigned b = (u & 0x80000000u) ? (u ^ 0x80000000u) : ~u;
    return __uint_as_float(b);
}

struct SmemT {
    union {
        struct {
            unsigned ctr[1024];          // 4KB: hist -> posBase cursors
            unsigned long long sk[KSEL]; // 2KB: survivors by bin segment
            unsigned cand[2048];         // 8KB: packed threshold-bin cands
        } f;
        unsigned long long all[2048];    // 16KB: exact fallback storage
    } u;
    float2 outVI[KSEL];                  // 2KB
    unsigned warpTot[8];
    unsigned s_b, s_rem;
    unsigned cntN;
};  // ~18.4KB

__global__ __launch_bounds__(NTHR, 6) void topk_kernel(
    const void* __restrict__ ids_raw,
    const float* __restrict__ W,
    float* __restrict__ out_val,
    float* __restrict__ out_idx)
{
    __shared__ SmemT s;
    const int tok  = blockIdx.x;
    const int tid  = threadIdx.x;
    const int lane = tid & 31;
    const int wrp  = tid >> 5;

    if (tid == 0) { s.cntN = 0u; s.s_b = SENT; }

    // ---- gather one embedding row (coalesced float4) ----
    long long id;
    if (g_ids64) id = ((const long long*)ids_raw)[tok];
    else         id = (long long)((const int*)ids_raw)[tok];

    const float4* row = (const float4*)(W + (size_t)id * HID);
    float4 a = __ldg(row + tid);
    float4 b = __ldg(row + tid + NTHR);

    unsigned key[8];
    key[0] = f2key(a.x); key[1] = f2key(a.y); key[2] = f2key(a.z); key[3] = f2key(a.w);
    key[4] = f2key(b.x); key[5] = f2key(b.y); key[6] = f2key(b.z); key[7] = f2key(b.w);

    // ---- filtered 11-bit histogram over bins [1024,2048) ----
    ((uint4*)s.u.f.ctr)[tid] = make_uint4(0u, 0u, 0u, 0u);   // 1024 words
    __syncthreads();

    #pragma unroll
    for (int e = 0; e < 8; e++)
        if (key[e] >= THR0)                       // <=> bin >= 1531 >= WBASE
            atomicAdd(&s.u.f.ctr[(key[e] >> 21) - WBASE], 1u);
    __syncthreads();

    // ---- suffix scan (4 bins/thread, single uint4) ----
    uint4 h = ((uint4*)s.u.f.ctr)[tid];
    unsigned bins[4] = {h.x, h.y, h.z, h.w};
    unsigned tsum = bins[0] + bins[1] + bins[2] + bins[3];

    unsigned sfx = tsum;                          // sum over lanes >= mine
    #pragma unroll
    for (int off = 1; off < 32; off <<= 1) {
        unsigned y = __shfl_down_sync(FULLW, sfx, off);
        if (lane + off < 32) sfx += y;
    }
    if (lane == 0) s.warpTot[wrp] = sfx;
    __syncthreads();

    unsigned hiW = 0;
    #pragma unroll
    for (int w = 0; w < 8; w++) hiW += (w > wrp) ? s.warpTot[w] : 0u;

    unsigned run = hiW + (sfx - tsum);
    unsigned pb[4];
    #pragma unroll
    for (int i = 3; i >= 0; i--) {
        unsigned hh = bins[i];
        pb[i] = run;
        if (run < KSEL && KSEL <= run + hh) {
            s.s_b   = (unsigned)(WBASE + tid * 4 + i);
            s.s_rem = KSEL - run;
        }
        run += hh;
    }
    __syncthreads();

    const unsigned bsel = s.s_b;

    if (bsel != SENT) {
        // ================= FAST PATH (always, in practice) =================
        const unsigned rem = s.s_rem;
        const int      nG  = (int)(KSEL - rem);

        // Seed scatter cursors with posBase (single uint4 store).
        ((uint4*)s.u.f.ctr)[tid] = make_uint4(pb[0], pb[1], pb[2], pb[3]);
        __syncthreads();

        // Scatter: d >= bsel >= 1531 implies the element passed the filter.
        #pragma unroll
        for (int e = 0; e < 8; e++) {
            unsigned k = key[e];
            unsigned d = k >> 21;
            if (d < bsel) continue;
            int idx = (e < 4) ? (tid * 4 + e) : ((tid + NTHR) * 4 + (e - 4));
            if (d > bsel) {
                unsigned slot = atomicAdd(&s.u.f.ctr[d - WBASE], 1u);
                s.u.f.sk[slot] = ((unsigned long long)k << 32) | (unsigned)(~idx);
            } else {
                unsigned slot = atomicAdd(&s.cntN, 1u);
                s.u.f.cand[slot] = ((k & 0x1FFFFFu) << 11) | (0x7FFu ^ (unsigned)idx);
            }
        }
        __syncthreads();

        const int n1 = (int)s.cntN;

        // Survivors: rank within own bin segment [ctr[d+1], ctr[d]).
        if (tid < nG) {
            unsigned long long my = s.u.f.sk[tid];
            const unsigned d = (unsigned)(my >> 53);
            unsigned lo = (d == 2047u) ? 0u : s.u.f.ctr[d + 1 - WBASE];
            unsigned hi2 = s.u.f.ctr[d - WBASE];
            int rank = 0;
            for (unsigned j = lo; j < hi2; j++)
                rank += (s.u.f.sk[j] > my);
            s.outVI[lo + rank] = make_float2(key2f((unsigned)(my >> 32)),
                                             (float)((int)(~(unsigned)my)));
        }

        // Threshold bin: rank-select top `rem` into slots [nG, 256).
        for (int t = tid; t < n1; t += NTHR) {
            unsigned my = s.u.f.cand[t];
            int rank = 0;
            for (int j = 0; j < n1; j++) rank += (s.u.f.cand[j] > my);
            if (rank < (int)rem) {
                unsigned k   = (bsel << 21) | (my >> 11);
                unsigned idx = 0x7FFu ^ (my & 0x7FFu);
                s.outVI[nG + rank] = make_float2(key2f(k), (float)idx);
            }
        }
    } else {
        // ====== EXACT FALLBACK (prob ~3e-14/token; brute force) ======
        __syncthreads();
        #pragma unroll
        for (int e = 0; e < 8; e++) {
            unsigned k = key[e];
            int idx = (e < 4) ? (tid * 4 + e) : ((tid + NTHR) * 4 + (e - 4));
            s.u.all[idx] = ((unsigned long long)k << 32) | (unsigned)(~idx);
        }
        __syncthreads();
        #pragma unroll
        for (int e = 0; e < 8; e++) {
            int idx = (e < 4) ? (tid * 4 + e) : ((tid + NTHR) * 4 + (e - 4));
            unsigned long long my = s.u.all[idx];
            int rank = 0;
            for (int j = 0; j < HID; j++) rank += (s.u.all[j] > my);
            if (rank < KSEL)
                s.outVI[rank] = make_float2(key2f((unsigned)(my >> 32)),
                                            (float)((int)(~(unsigned)my)));
        }
    }
    __syncthreads();

    // ---- single fully-coalesced global write ----
    float2 r = s.outVI[tid];
    out_val[(size_t)tok * KSEL + tid] = r.x;
    out_idx[(size_t)tok * KSEL + tid] = r.y;
}

extern "C" void kernel_launch(void* const* d_in, const int* in_sizes, int n_in,
                              void* d_out, int out_size)
{
    const void*  ids = d_in[0];
    const float* W   = (const float*)d_in[1];

    float* out_val = (float*)d_out;
    float* out_idx = (float*)d_out + (size_t)NTOK * KSEL;

    detect_ids_kernel<<<1, NTHR>>>((const unsigned int*)ids);
    topk_kernel<<<NTOK, NTHR>>>(ids, W, out_val, out_idx);
}